// round 12
// baseline (speedup 1.0000x reference)
#include <cuda_runtime.h>
#include <math.h>

#define B_ 128
#define T_ 1024
#define D_ 128
#define U_ 256
#define M_ 64

// Static device scratch (no cudaMalloc anywhere)
// Layout: [t][bg(16)][sl(8)][g(4)][b(8)][c(32)]  (CTA-contiguous blocks)
__device__ float g_X[134217728];

// ---------------------------------------------------------------------------
// f32x2 packed helpers
// ---------------------------------------------------------------------------
__device__ __forceinline__ void fma2(unsigned long long& d,
                                     unsigned long long a,
                                     unsigned long long b) {
    asm("fma.rn.f32x2 %0, %1, %2, %0;" : "+l"(d) : "l"(a), "l"(b));
}
__device__ __forceinline__ float sum2(unsigned long long v) {
    return __uint_as_float((unsigned)v) + __uint_as_float((unsigned)(v >> 32));
}
__device__ __forceinline__ unsigned long long pk2(float a, float b) {
    unsigned long long r;
    asm("mov.b64 %0, {%1, %2};" : "=l"(r) : "f"(a), "f"(b));
    return r;
}
__device__ __forceinline__ unsigned smu32(const void* p) {
    return (unsigned)__cvta_generic_to_shared(p);
}

// ---- mbarrier primitives ----
__device__ __forceinline__ void mb_init(unsigned mbar, unsigned count) {
    asm volatile("mbarrier.init.shared.b64 [%0], %1;"
                 :: "r"(mbar), "r"(count) : "memory");
}
__device__ __forceinline__ void mb_expect_tx(unsigned mbar, unsigned bytes) {
    asm volatile("mbarrier.arrive.expect_tx.shared.b64 _, [%0], %1;"
                 :: "r"(mbar), "r"(bytes) : "memory");
}
__device__ __forceinline__ void mb_wait(unsigned mbar, unsigned parity) {
    unsigned done;
    asm volatile(
        "{\n\t.reg .pred p;\n\t"
        "mbarrier.try_wait.parity.acquire.cta.shared::cta.b64 p, [%1], %2;\n\t"
        "selp.b32 %0, 1, 0, p;\n\t}"
        : "=r"(done) : "r"(mbar), "r"(parity) : "memory");
    while (!done) {
        asm volatile(
            "{\n\t.reg .pred p;\n\t"
            "mbarrier.try_wait.parity.acquire.cta.shared::cta.b64 p, [%1], %2, 0x989680;\n\t"
            "selp.b32 %0, 1, 0, p;\n\t}"
            : "=r"(done) : "r"(mbar), "r"(parity) : "memory");
    }
}

// ---------------------------------------------------------------------------
// K1 v2: one block per timestep. Input tile resident in smem; 16 weight
// tiles (g, u0) double-buffered through smem. 512 threads, 4u x 4b microtile.
// ---------------------------------------------------------------------------
#define P_ISH_STR 130
#define P_WSH_STR 68
#define P_ISH_OFF 0
#define P_WSH_OFF (128 * P_ISH_STR)               // two buffers follow
#define P_WBUF    (128 * P_WSH_STR)
#define K1_SMEM_BYTES ((128 * P_ISH_STR + 2 * P_WBUF) * 4)   // 136,192 B

__global__ void __launch_bounds__(512) proj_kernel(
    const float* __restrict__ inp,
    const float* __restrict__ Wi, const float* __restrict__ Wf,
    const float* __restrict__ Wc, const float* __restrict__ Wo,
    const float* __restrict__ bi, const float* __restrict__ bf,
    const float* __restrict__ bc, const float* __restrict__ bo)
{
    extern __shared__ float sm[];
    float* Ish = sm + P_ISH_OFF;     // [b=128][130]
    float* Wsh = sm + P_WSH_OFF;     // 2 x [d=128][68]

    const int t   = blockIdx.x;
    const int tid = threadIdx.x;

    const float* Wmat[4] = { Wi, Wf, Wc, Wo };
    const float* bvec[4] = { bi, bf, bc, bo };

    // input tile: [b][d], coalesced in d
    for (int i = tid; i < 128 * 128; i += 512) {
        int b = i >> 7, d = i & 127;
        Ish[b * P_ISH_STR + d] = inp[((size_t)b * T_ + t) * D_ + d];
    }

    // preload weight tile 0 into buffer 0 (tile: g = tl>>2, u0 = (tl&3)*64)
    {
        const float* W = Wmat[0];
#pragma unroll
        for (int k = 0; k < 4; k++) {
            int fi = tid + 512 * k;          // 2048 float4 per tile
            int d  = fi >> 4, u4 = fi & 15;
            float4 v = *(const float4*)&W[(size_t)d * U_ + u4 * 4];
            *(float4*)&Wsh[d * P_WSH_STR + u4 * 4] = v;
        }
    }
    __syncthreads();

    const int j4 = (tid & 15) * 4;           // 64 u per tile
    const int b4 = (tid >> 4) * 4;           // 32 groups * 4 = 128 b

    for (int tl = 0; tl < 16; tl++) {
        const int g  = tl >> 2;
        const int u0 = (tl & 3) * 64;
        float* Wcur = Wsh + (tl & 1) * P_WBUF;

        // prefetch next tile into registers (hidden behind compute)
        float4 wpre[4];
        if (tl + 1 < 16) {
            const int ng  = (tl + 1) >> 2;
            const int nu0 = ((tl + 1) & 3) * 64;
            const float* W = Wmat[ng];
#pragma unroll
            for (int k = 0; k < 4; k++) {
                int fi = tid + 512 * k;
                int d  = fi >> 4, u4 = fi & 15;
                wpre[k] = *(const float4*)&W[(size_t)d * U_ + nu0 + u4 * 4];
            }
        }

        // compute: 4 u x 4 b, K = 128, f32x2
        unsigned long long acc[4][4];
#pragma unroll
        for (int jj = 0; jj < 4; jj++)
#pragma unroll
            for (int bb = 0; bb < 4; bb++) acc[jj][bb] = 0ull;

#pragma unroll 8
        for (int d = 0; d < 128; d += 2) {
            float4 wa = *(const float4*)&Wcur[d * P_WSH_STR + j4];
            float4 wb = *(const float4*)&Wcur[(d + 1) * P_WSH_STR + j4];
            unsigned long long w0 = pk2(wa.x, wb.x), w1 = pk2(wa.y, wb.y);
            unsigned long long w2 = pk2(wa.z, wb.z), w3 = pk2(wa.w, wb.w);
#pragma unroll
            for (int bb = 0; bb < 4; bb++) {
                unsigned long long iv = *(const unsigned long long*)
                    &Ish[(b4 + bb) * P_ISH_STR + d];
                fma2(acc[0][bb], w0, iv);
                fma2(acc[1][bb], w1, iv);
                fma2(acc[2][bb], w2, iv);
                fma2(acc[3][bb], w3, iv);
            }
        }

        // store to g_X: [t][bg][sl][g][b][c]
        const int u   = u0 + j4;
        const int slo = u >> 5;
        const int co  = u & 31;
        const float bv0 = bvec[g][u + 0], bv1 = bvec[g][u + 1];
        const float bv2 = bvec[g][u + 2], bv3 = bvec[g][u + 3];
#pragma unroll
        for (int bb = 0; bb < 4; bb++) {
            int bfull = b4 + bb;
            float* p = g_X + (size_t)t * 131072 + (size_t)(bfull >> 3) * 8192 +
                       slo * 1024 + g * 256 + (bfull & 7) * 32 + co;
            *(float4*)p = make_float4(sum2(acc[0][bb]) + bv0,
                                      sum2(acc[1][bb]) + bv1,
                                      sum2(acc[2][bb]) + bv2,
                                      sum2(acc[3][bb]) + bv3);
        }

        // commit prefetched tile to the other buffer, then switch
        if (tl + 1 < 16) {
            float* Wnxt = Wsh + ((tl + 1) & 1) * P_WBUF;
#pragma unroll
            for (int k = 0; k < 4; k++) {
                int fi = tid + 512 * k;
                int d  = fi >> 4, u4 = fi & 15;
                *(float4*)&Wnxt[d * P_WSH_STR + u4 * 4] = wpre[k];
            }
            __syncthreads();
        }
    }
}

// ---------------------------------------------------------------------------
// K2: persistent recurrence — byte-identical to the R10 winner (6982 us).
// ---------------------------------------------------------------------------
#define SMW_F4   10240                       // 163,840 B weights
#define SHH_OFF  40960                       // [2][src 8][264] floats
#define SHH_SRC  264
#define SHH_BUF  (8 * SHH_SRC)               // 2112 floats per buffer
#define ZB_OFF   (SHH_OFF + 2 * SHH_BUF)     // 45184: [8][5][8][32]
#define HST_OFF  (ZB_OFF + 8 * 5 * 8 * 32)   // 55424: [2][256]
#define MBAR_OFF (HST_OFF + 512)             // 55936: 8 mbarriers
#define R_SMEM_BYTES ((MBAR_OFF + 16) * 4)   // 223,808 B

__global__ void __launch_bounds__(640, 1) __cluster_dims__(8, 1, 1)
recur_kernel(const float* __restrict__ Ui, const float* __restrict__ Uf,
             const float* __restrict__ Uc, const float* __restrict__ Uo,
             const float* __restrict__ Wmem, const float* __restrict__ Umem,
             float* __restrict__ out)
{
    extern __shared__ float sm[];
    float4* wsm4 = (float4*)sm;
    float*  shh  = sm + SHH_OFF;
    float*  zb   = sm + ZB_OFF;
    float*  hst  = sm + HST_OFF;

    const int bg   = blockIdx.x >> 3;
    const int sl   = blockIdx.x & 7;
    const int tid  = threadIdx.x;
    const int g    = tid >> 7;               // 0..4  matrix
    const int kq8  = (tid >> 4) & 7;         // 0..7  K-eighth == source slice
    const int cp   = tid & 15;               // column pair

    const unsigned smb   = smu32(sm);
    const unsigned shh_u = smb + SHH_OFF * 4;
    const unsigned hst_u = smb + HST_OFF * 4;
    const unsigned mb0   = smb + MBAR_OFF * 4;    // mbar[q] = mb0 + q*8
    const unsigned my_mb = mb0 + (unsigned)kq8 * 8;
    const bool     poster = (g == 0 && cp == 0);

    // ---- mbarrier init ----
    if (tid < 8) mb_init(mb0 + tid * 8, 1);
    __syncthreads();

    // pusher warp 8 (tid 256..287): lanes 0..7 own one peer each
    unsigned rd_base = 0, rm_peer = 0;
    if (tid >= 256 && tid < 264) {
        const int peer = tid - 256;
        asm("mapa.shared::cluster.u32 %0, %1, %2;" : "=r"(rd_base)
            : "r"(shh_u + (unsigned)(sl * SHH_SRC * 4)), "r"(peer));
        asm("mapa.shared::cluster.u32 %0, %1, %2;" : "=r"(rm_peer)
            : "r"(mb0 + (unsigned)(sl * 8)), "r"(peer));
    }

    // ---- weights into SMEM, f32x2-paired layout ----
    for (int idx = tid; idx < SMW_F4; idx += 640) {
        int lcp = idx & 15;
        int p   = (idx >> 4) & 1;
        int j   = (idx >> 5) & 7;
        int q8  = (idx >> 8) & 7;
        int gg  = idx >> 11;
        int k   = q8 * 32 + j * 4 + 2 * p;
        int col = sl * 32 + lcp * 2;
        float4 v;
        if (gg < 4) {
            const float* W = (gg == 0) ? Ui : (gg == 1) ? Uf :
                             (gg == 2) ? Uc : Uo;
            v.x = W[(size_t)k * 256 + col];
            v.y = W[(size_t)(k + 1) * 256 + col];
            v.z = W[(size_t)k * 256 + col + 1];
            v.w = W[(size_t)(k + 1) * 256 + col + 1];
        } else {
            float s00 = 0.f, s10 = 0.f, s01 = 0.f, s11 = 0.f;
#pragma unroll 8
            for (int m = 0; m < M_; m++) {
                float u0 = Umem[k * M_ + m];
                float u1 = Umem[(k + 1) * M_ + m];
                float w0 = Wmem[m * U_ + col];
                float w1 = Wmem[m * U_ + col + 1];
                s00 = fmaf(u0, w0, s00); s10 = fmaf(u1, w0, s10);
                s01 = fmaf(u0, w1, s01); s11 = fmaf(u1, w1, s11);
            }
            v.x = 0.1f * s00; v.y = 0.1f * s10;
            v.z = 0.1f * s01; v.w = 0.1f * s11;
        }
        wsm4[idx] = v;
    }
    for (int i = tid; i < 2 * SHH_BUF; i += 640) shh[i] = 0.f;

    // gate-thread persistent quantities (tid < 256)
    const int gb  = tid >> 5;
    const int gcc = tid & 31;
    const float* xbase = g_X + (size_t)bg * 8192 + sl * 1024 + gb * 32 + gcc;
    float creg = 0.f, rreg = 0.f;
    float xc0 = 0.f, xc1 = 0.f, xc2 = 0.f, xc3 = 0.f;
    float* outp = out + ((size_t)(bg * 8 + gb) * T_) * U_ + sl * 32 + gcc;

    if (tid < 256) {                        // x for t = 0 into registers
        xc0 = xbase[0];
        xc1 = xbase[256];
        xc2 = xbase[512];
        xc3 = xbase[768];
    }
    if (poster) mb_expect_tx(my_mb, 1024);   // phase 0 (consumed at t=1)
    __syncthreads();
    asm volatile("barrier.cluster.arrive.aligned;" ::: "memory");
    asm volatile("barrier.cluster.wait.aligned;" ::: "memory");

    const float4* wp   = wsm4 + (g * 8 + kq8) * 256 + cp;
    float*        zrow = zb + (kq8 * 5 + g) * 256 + cp * 2;

    for (int t = 0; t < T_; t++) {
        const int cur = t & 1;
        const float* hsrc = shh + cur * SHH_BUF + kq8 * SHH_SRC;

        // ---- prefetch x_{t+1} into registers (no h dependency) ----
        float xr0, xr1, xr2, xr3;
        const bool pf = (tid < 256) && (t + 1 < T_);
        if (pf) {
            const float* xp = xbase + (size_t)(t + 1) * 131072;
            xr0 = xp[0]; xr1 = xp[256]; xr2 = xp[512]; xr3 = xp[768];
        }

        // ---- wait for my source slice of h (phase t-1), repost expect ----
        if (t > 0) {
            mb_wait(my_mb, (unsigned)((t - 1) & 1));
            if (poster) mb_expect_tx(my_mb, 1024);
        }

        // ---- z = h_prev @ W : 2 cols, 32 K, 8 b per thread (f32x2) ----
        unsigned long long a0[8], a1[8];
#pragma unroll
        for (int b = 0; b < 8; b++) { a0[b] = 0ull; a1[b] = 0ull; }
#pragma unroll
        for (int j = 0; j < 8; j++) {
            ulonglong2 wa = *(const ulonglong2*)(wp + j * 32);
            ulonglong2 wb = *(const ulonglong2*)(wp + j * 32 + 16);
#pragma unroll
            for (int b = 0; b < 8; b++) {
                ulonglong2 hh =
                    *(const ulonglong2*)(hsrc + b * 32 + j * 4);
                fma2(a0[b], wa.x, hh.x); fma2(a1[b], wa.y, hh.x);
                fma2(a0[b], wb.x, hh.y); fma2(a1[b], wb.y, hh.y);
            }
        }
#pragma unroll
        for (int b = 0; b < 8; b++) {
            float2 z2 = make_float2(sum2(a0[b]), sum2(a1[b]));
            *(float2*)(zrow + b * 32) = z2;
        }
        __syncthreads();                      // zbuf complete

        // ---- gates + state (tid<256) ; pusher warp (256..287) parks ----
        if (tid < 256) {
            float zi = 0, zf = 0, zc = 0, zo = 0, zr = 0;
#pragma unroll
            for (int q = 0; q < 8; q++) {
                const float* zq = zb + q * 5 * 256 + gb * 32 + gcc;
                zi += zq[0];
                zf += zq[256];
                zc += zq[512];
                zo += zq[768];
                zr += zq[1024];
            }
            float rn = rreg + zr;
            float pi  = xc0 + zi + rn;
            float pff = xc1 + zf;
            float pc  = xc2 + zc;
            float po  = xc3 + zo;
            float ig = __fdividef(1.f, 1.f + __expf(-pi));
            float fg = __fdividef(1.f, 1.f + __expf(-pff));
            float ct = __fdividef(2.f, 1.f + __expf(-2.f * pc)) - 1.f;
            float og = __fdividef(1.f, 1.f + __expf(-po));
            float cn = fg * creg + ig * ct;
            float hv = og * (__fdividef(2.f, 1.f + __expf(-2.f * cn)) - 1.f);
            creg = cn;
            rreg = rn;
            hst[cur * 256 + tid] = hv;
            if (pf) { xc0 = xr0; xc1 = xr1; xc2 = xr2; xc3 = xr3; }

            asm volatile("bar.sync 1, 288;" ::: "memory");

            outp[(size_t)t * U_] = hv;        // off the push critical path
        } else if (tid < 288) {
            // pusher warp: wait for gates' hst, then fire 8 bulk copies
            asm volatile("bar.sync 1, 288;" ::: "memory");
            if (tid < 264 && t + 1 < T_) {
                asm volatile("fence.proxy.async.shared::cta;" ::: "memory");
                unsigned dst = rd_base +
                    (unsigned)(((t + 1) & 1) * SHH_BUF * 4);
                unsigned src = hst_u + (unsigned)(cur * 1024);
                asm volatile(
                    "cp.async.bulk.shared::cluster.shared::cta"
                    ".mbarrier::complete_tx::bytes [%0], [%1], %2, [%3];"
                    :: "r"(dst), "r"(src), "r"(1024u), "r"(rm_peer)
                    : "memory");
            }
        }
    }

    // no CTA may exit while peers' bulk copies into its SMEM are in flight
    asm volatile("barrier.cluster.arrive.aligned;" ::: "memory");
    asm volatile("barrier.cluster.wait.aligned;" ::: "memory");
}

// ---------------------------------------------------------------------------
// Launcher: capture-legal (exactly 2 kernel launches, default stream)
// ---------------------------------------------------------------------------
extern "C" void kernel_launch(void* const* d_in, const int* in_sizes, int n_in,
                              void* d_out, int out_size)
{
    const float* inp  = (const float*)d_in[0];
    const float* Wi   = (const float*)d_in[1];
    const float* Wf   = (const float*)d_in[2];
    const float* Wc   = (const float*)d_in[3];
    const float* Wo   = (const float*)d_in[4];
    const float* Uig  = (const float*)d_in[5];
    const float* Ufg  = (const float*)d_in[6];
    const float* Ucg  = (const float*)d_in[7];
    const float* Uog  = (const float*)d_in[8];
    const float* Wmem = (const float*)d_in[9];
    const float* Umem = (const float*)d_in[10];
    const float* bi   = (const float*)d_in[11];
    const float* bf   = (const float*)d_in[12];
    const float* bc   = (const float*)d_in[13];
    const float* bo   = (const float*)d_in[14];
    float* out = (float*)d_out;

    cudaFuncSetAttribute(proj_kernel,
                         cudaFuncAttributeMaxDynamicSharedMemorySize,
                         K1_SMEM_BYTES);
    proj_kernel<<<1024, 512, K1_SMEM_BYTES, 0>>>(inp, Wi, Wf, Wc, Wo,
                                                 bi, bf, bc, bo);

    cudaFuncSetAttribute(recur_kernel,
                         cudaFuncAttributeMaxDynamicSharedMemorySize,
                         R_SMEM_BYTES);
    recur_kernel<<<128, 640, R_SMEM_BYTES, 0>>>(Uig, Ufg, Ucg, Uog,
                                                Wmem, Umem, out);
}